// round 6
// baseline (speedup 1.0000x reference)
#include <cuda_runtime.h>

#define NB 32
#define NQ 1024
#define NG 64
#define NT 128           // threads per solver CTA
#define KPT 8            // columns per thread
#define BIG 1e300
#define MARGIN 1e-2f

// 8 MB scratch: transposed cost cost[b][i][j], i = gt row, j = proposal col
__device__ float g_cost[NB * NG * NQ];

// ---------------------------------------------------------------------------
// Cost build (exact IEEE order, no FMA contraction -> bit-matches reference fp32)
// ---------------------------------------------------------------------------
__global__ void build_cost_kernel(const float* __restrict__ obj,
                                  const float* __restrict__ cd,
                                  const float* __restrict__ gi) {
    int t = blockIdx.x * blockDim.x + threadIdx.x;
    if (t >= NB * NG * NQ) return;
    int j = t & (NQ - 1);
    int i = (t >> 10) & (NG - 1);
    int b = t >> 16;
    float o = obj[b * NQ + j];
    int src = (b * NQ + j) * NG + i;
    float a0 = __fmul_rn(5.0f, -o);
    float a1 = __fmul_rn(10.0f, cd[src]);
    float a2 = __fmul_rn(2.0f, -gi[src]);
    g_cost[t] = __fadd_rn(__fadd_rn(a0, a1), a2);
}

// Order-preserving uint64 key for a double, column index in low 10 bits
// (near-equal values tie toward the smaller index == numpy first-min rule).
__device__ __forceinline__ unsigned long long packkey(double x, int idx) {
    long long sb = __double_as_longlong(x);
    unsigned long long ub = (unsigned long long)sb;
    ub = (sb < 0) ? ~ub : (ub | 0x8000000000000000ULL);
    return (ub & ~1023ULL) | (unsigned long long)idx;
}

// ---------------------------------------------------------------------------
// Jonker-Volgenant shortest-augmenting-path LSA, one CTA per batch.
// Transposed: n = g rows (gt), m = 1024 cols (proposals).
// Warp-uniform fp32 ballot prefilter -> fp64 exact path only where needed.
// 1 barrier per Dijkstra step; per-warp packed-key argmin, 4-slot reset ring.
// ---------------------------------------------------------------------------
__global__ void __launch_bounds__(NT, 1)
solve_kernel(const int* __restrict__ ngt, float* __restrict__ out) {
    const int b = blockIdx.x;
    const int tid = threadIdx.x;
    const int w = tid >> 5;

    __shared__ double s_short[NQ];           // exact fp64 shortest
    __shared__ short  s_row4col[NQ];
    __shared__ unsigned char s_path[NQ];
    __shared__ double s_u[NG];
    __shared__ float  s_uf[NG];
    __shared__ short  s_col4row[NG];
    __shared__ unsigned char s_inSR[NG];
    __shared__ unsigned long long s_pack[4][4];   // [ring][warp]

    float* outi = out + b * NQ;              // per_prop_gt_inds (as float)
    float* outm = out + NB * NQ + b * NQ;    // proposal_matched_mask

    for (int j = tid; j < NQ; j += NT) { outi[j] = 0.0f; outm[j] = 0.0f; }

    const int g = ngt[b];
    if (g <= 0) return;

    const float* __restrict__ cost = g_cost + b * NG * NQ;

    // one-time L1 warm of this CTA's 256KB cost slice (one touch per 32B sector)
    for (int off = tid * 8; off < NG * NQ; off += NT * 8) {
        float dummy;
        asm volatile("ld.global.f32 %0, [%1];" : "=f"(dummy) : "l"(cost + off));
    }

    double v_reg[KPT], sh_reg[KPT];
    float  vf[KPT], shf[KPT];
#pragma unroll
    for (int k = 0; k < KPT; ++k) { v_reg[k] = 0.0; vf[k] = 0.0f; }

    for (int j = tid; j < NQ; j += NT) s_row4col[j] = -1;
    for (int i = tid; i < g; i += NT) { s_u[i] = 0.0; s_uf[i] = 0.0f; s_col4row[i] = -1; }
    if (tid < 16) s_pack[tid >> 2][tid & 3] = ~0ULL;

    int t = 0;   // global step counter (ring phase), continuous across Dijkstras
    __syncthreads();

    for (int cur = 0; cur < g; ++cur) {
        unsigned scmask = 0;
        double lbest = BIG;
        int lidx = 0;
#pragma unroll
        for (int k = 0; k < KPT; ++k) { sh_reg[k] = BIG; shf[k] = 3e38f; }
        for (int i = tid; i < g; i += NT) s_inSR[i] = (i == cur) ? 1 : 0;
        __syncthreads();

        int i = cur;
        double mvd = 0.0;
        float  mvf = 0.0f;
        int sink;

        // ---- Dijkstra over columns: 1 barrier per step ----
        while (true) {
            const float  scalf = mvf - s_uf[i];
            const double u_i = s_u[i];
            const float* __restrict__ crow = cost + i * NQ;

#pragma unroll
            for (int k = 0; k < KPT; ++k) {
                const int j = tid + (k << 7);
                const float cf = __ldg(crow + j);
                // fp32 prefilter; visited columns excluded via scmask
                const bool cand = !((scmask >> k) & 1u) &&
                                  ((scalf + cf) - vf[k] < shf[k] + MARGIN);
                // warp-uniform branch: skip fp64 entirely when no lane qualifies
                if (__ballot_sync(0xffffffffu, cand)) {
                    if (cand) {
                        // exact path, reference rounding order: ((mv + c) - u) - v
                        double r = ((mvd + (double)cf) - u_i) - v_reg[k];
                        if (r < sh_reg[k]) {
                            sh_reg[k] = r;
                            shf[k] = (float)r;
                            s_short[j] = r;
                            s_path[j] = (unsigned char)i;
                            if (r < lbest) { lbest = r; lidx = j; }
                        }
                    }
                }
            }
            if (lbest < BIG) atomicMin(&s_pack[t & 3][w], packkey(lbest, lidx));
            __syncthreads();

            // all threads combine the 4 warp cells
            unsigned long long p  = s_pack[t & 3][0];
            unsigned long long q1 = s_pack[t & 3][1];
            unsigned long long q2 = s_pack[t & 3][2];
            unsigned long long q3 = s_pack[t & 3][3];
            if (q1 < p) p = q1;
            if (q2 < p) p = q2;
            if (q3 < p) p = q3;
            const int bidx = (int)(p & 1023ULL);

            if (tid < 4) s_pack[(t + 2) & 3][tid] = ~0ULL;   // barrier-ordered reset

            mvd = s_short[bidx];
            mvf = (float)mvd;
            const int rc = s_row4col[bidx];

            // owner removes the visited column and rescans its registers
            if ((bidx & (NT - 1)) == tid) {
                const int kk = bidx >> 7;
                scmask |= 1u << kk;
                lbest = BIG; lidx = 0;
#pragma unroll
                for (int k = 0; k < KPT; ++k) {
                    if (!((scmask >> k) & 1u) && sh_reg[k] < lbest) {
                        lbest = sh_reg[k];
                        lidx = tid + (k << 7);
                    }
                }
            }
            ++t;
            if (rc < 0) { sink = bidx; break; }
            if (tid == 0) s_inSR[rc] = 1;
            i = rc;
        }

        // ---- dual updates (pre-augment col4row) ----
#pragma unroll
        for (int k = 0; k < KPT; ++k) {
            if ((scmask >> k) & 1u) {
                v_reg[k] -= (mvd - sh_reg[k]);
                vf[k] = (float)v_reg[k];
            }
        }
        for (int ii = tid; ii < g; ii += NT) {
            if (ii == cur) {
                s_u[ii] += mvd;
                s_uf[ii] = (float)s_u[ii];
            } else if (s_inSR[ii]) {
                s_u[ii] += (mvd - s_short[s_col4row[ii]]);
                s_uf[ii] = (float)s_u[ii];
            }
        }
        __syncthreads();

        // ---- augment alternating path (serial, short) ----
        if (tid == 0) {
            int j = sink;
            while (true) {
                const int ii = s_path[j];
                s_row4col[j] = (short)ii;
                const short nj = s_col4row[ii];
                s_col4row[ii] = (short)j;
                j = nj;
                if (ii == cur) break;
            }
        }
        __syncthreads();
    }

    // outputs: proposal p = col4row[i] gets index i, mask 1
    for (int i = tid; i < g; i += NT) {
        const int p = s_col4row[i];
        outi[p] = (float)i;
        outm[p] = 1.0f;
    }
}

extern "C" void kernel_launch(void* const* d_in, const int* in_sizes, int n_in,
                              void* d_out, int out_size) {
    const float* obj = (const float*)d_in[1];
    const float* cd  = (const float*)d_in[2];
    const float* gi  = (const float*)d_in[3];
    const int* ngt   = (const int*)d_in[4];
    float* out = (float*)d_out;

    const int total = NB * NG * NQ;
    build_cost_kernel<<<(total + 255) / 256, 256>>>(obj, cd, gi);
    solve_kernel<<<NB, NT>>>(ngt, out);
}

// round 8
// speedup vs baseline: 1.1727x; 1.1727x over previous
#include <cuda_runtime.h>

#define NB 32
#define NQ 1024
#define NG 64
#define NT 128           // threads per solver CTA
#define KPT 8            // columns per thread
#define BIG 1e300

// 8 MB scratch: transposed cost cost[b][i][j], i = gt row, j = proposal col
__device__ float g_cost[NB * NG * NQ];

// ---------------------------------------------------------------------------
// Cost build (exact IEEE order, no FMA contraction -> bit-matches reference fp32)
// ---------------------------------------------------------------------------
__global__ void build_cost_kernel(const float* __restrict__ obj,
                                  const float* __restrict__ cd,
                                  const float* __restrict__ gi) {
    int t = blockIdx.x * blockDim.x + threadIdx.x;
    if (t >= NB * NG * NQ) return;
    int j = t & (NQ - 1);
    int i = (t >> 10) & (NG - 1);
    int b = t >> 16;
    float o = obj[b * NQ + j];
    int src = (b * NQ + j) * NG + i;
    float a0 = __fmul_rn(5.0f, -o);
    float a1 = __fmul_rn(10.0f, cd[src]);
    float a2 = __fmul_rn(2.0f, -gi[src]);
    g_cost[t] = __fadd_rn(__fadd_rn(a0, a1), a2);
}

// Order-preserving uint64 key for a double, column index in low 10 bits
// (near-equal values tie toward the smaller index == numpy first-min rule).
__device__ __forceinline__ unsigned long long packkey(double x, int idx) {
    long long sb = __double_as_longlong(x);
    unsigned long long ub = (unsigned long long)sb;
    ub = (sb < 0) ? ~ub : (ub | 0x8000000000000000ULL);
    return (ub & ~1023ULL) | (unsigned long long)idx;
}

// ---------------------------------------------------------------------------
// Jonker-Volgenant shortest-augmenting-path LSA, one CTA per batch.
// Transposed: n = g rows (gt), m = 1024 cols (proposals).
// Pure-fp64 relax (R2-proven); per-warp packed-key atomicMin cells;
// all-thread combine; ONE barrier per Dijkstra step via 4-slot reset ring.
// ---------------------------------------------------------------------------
__global__ void __launch_bounds__(NT, 1)
solve_kernel(const int* __restrict__ ngt, float* __restrict__ out) {
    const int b = blockIdx.x;
    const int tid = threadIdx.x;
    const int w = tid >> 5;

    __shared__ double s_short[NQ];           // exact fp64 shortest (write-through)
    __shared__ short  s_row4col[NQ];
    __shared__ unsigned char s_path[NQ];
    __shared__ double s_u[NG];
    __shared__ short  s_col4row[NG];
    __shared__ unsigned char s_inSR[NG];
    __shared__ unsigned long long s_pack[4][4];   // [ring slot][warp]

    float* outi = out + b * NQ;              // per_prop_gt_inds (as float)
    float* outm = out + NB * NQ + b * NQ;    // proposal_matched_mask

    for (int j = tid; j < NQ; j += NT) { outi[j] = 0.0f; outm[j] = 0.0f; }

    const int g = ngt[b];
    if (g <= 0) return;

    const float* __restrict__ cost = g_cost + b * NG * NQ;

    // one-time L1 warm of this CTA's 256KB cost slice (one touch per 32B sector)
    for (int off = tid * 8; off < NG * NQ; off += NT * 8) {
        float dummy;
        asm volatile("ld.global.f32 %0, [%1];" : "=f"(dummy) : "l"(cost + off));
    }

    double v_reg[KPT], sh_reg[KPT];
#pragma unroll
    for (int k = 0; k < KPT; ++k) v_reg[k] = 0.0;

    for (int j = tid; j < NQ; j += NT) s_row4col[j] = -1;
    for (int i = tid; i < g; i += NT) { s_u[i] = 0.0; s_col4row[i] = -1; }
    if (tid < 16) s_pack[tid >> 2][tid & 3] = ~0ULL;

    int t = 0;   // global step counter (ring phase), continuous across Dijkstras
    __syncthreads();

    for (int cur = 0; cur < g; ++cur) {
        unsigned scmask = 0;
        double lbest = BIG;
        int lidx = 0;
#pragma unroll
        for (int k = 0; k < KPT; ++k) sh_reg[k] = BIG;
        for (int i = tid; i < g; i += NT) s_inSR[i] = (i == cur) ? 1 : 0;
        __syncthreads();

        int i = cur;
        double mvd = 0.0;
        int sink;

        // ---- Dijkstra over columns: ONE barrier per step ----
        while (true) {
            const double scal = mvd - s_u[i];            // broadcast LDS
            const float* __restrict__ crow = cost + i * NQ;

#pragma unroll
            for (int k = 0; k < KPT; ++k) {
                if (!((scmask >> k) & 1u)) {
                    const int j = tid + (k << 7);
                    double r = (scal + (double)__ldg(crow + j)) - v_reg[k];
                    if (r < sh_reg[k]) {
                        sh_reg[k] = r;
                        s_short[j] = r;
                        s_path[j] = (unsigned char)i;
                        if (r < lbest) { lbest = r; lidx = j; }
                    }
                }
            }
            if (lbest < BIG) atomicMin(&s_pack[t & 3][w], packkey(lbest, lidx));
            __syncthreads();

            // all threads combine the 4 warp cells
            unsigned long long p  = s_pack[t & 3][0];
            unsigned long long q1 = s_pack[t & 3][1];
            unsigned long long q2 = s_pack[t & 3][2];
            unsigned long long q3 = s_pack[t & 3][3];
            if (q1 < p) p = q1;
            if (q2 < p) p = q2;
            if (q3 < p) p = q3;
            const int bidx = (int)(p & 1023ULL);

            if (tid < 4) s_pack[(t + 2) & 3][tid] = ~0ULL;   // barrier-ordered reset

            mvd = s_short[bidx];                 // exact shortest value (broadcast)
            const int rc = s_row4col[bidx];

            // owner removes the visited column and rescans its registers
            if ((bidx & (NT - 1)) == tid) {
                const int kk = bidx >> 7;
                scmask |= 1u << kk;
                lbest = BIG; lidx = 0;
#pragma unroll
                for (int k = 0; k < KPT; ++k) {
                    if (!((scmask >> k) & 1u) && sh_reg[k] < lbest) {
                        lbest = sh_reg[k];
                        lidx = tid + (k << 7);
                    }
                }
            }
            ++t;
            if (rc < 0) { sink = bidx; break; }
            if (tid == 0) s_inSR[rc] = 1;
            i = rc;
        }

        // ---- dual updates (pre-augment col4row) ----
#pragma unroll
        for (int k = 0; k < KPT; ++k) {
            if ((scmask >> k) & 1u) v_reg[k] -= (mvd - sh_reg[k]);
        }
        for (int ii = tid; ii < g; ii += NT) {
            if (ii == cur) s_u[ii] += mvd;
            else if (s_inSR[ii]) s_u[ii] += (mvd - s_short[s_col4row[ii]]);
        }
        __syncthreads();

        // ---- augment alternating path (serial, short) ----
        if (tid == 0) {
            int j = sink;
            while (true) {
                const int ii = s_path[j];
                s_row4col[j] = (short)ii;
                const short nj = s_col4row[ii];
                s_col4row[ii] = (short)j;
                j = nj;
                if (ii == cur) break;
            }
        }
        __syncthreads();
    }

    // outputs: proposal p = col4row[i] gets index i, mask 1
    for (int i = tid; i < g; i += NT) {
        const int p = s_col4row[i];
        outi[p] = (float)i;
        outm[p] = 1.0f;
    }
}

extern "C" void kernel_launch(void* const* d_in, const int* in_sizes, int n_in,
                              void* d_out, int out_size) {
    const float* obj = (const float*)d_in[1];
    const float* cd  = (const float*)d_in[2];
    const float* gi  = (const float*)d_in[3];
    const int* ngt   = (const int*)d_in[4];
    float* out = (float*)d_out;

    const int total = NB * NG * NQ;
    build_cost_kernel<<<(total + 255) / 256, 256>>>(obj, cd, gi);
    solve_kernel<<<NB, NT>>>(ngt, out);
}